// round 5
// baseline (speedup 1.0000x reference)
#include <cuda_runtime.h>
#include <cuda_bf16.h>
#include <cstdint>

#define BATCH 8
#define DIM   128
#define NTOK  32768
#define SPLIT 16
#define CHUNK (NTOK/SPLIT)     // 2048 tokens per CTA
#define ITERS (CHUNK/64)       // 32 stages of 64 tokens
#define EPS 1e-8f

typedef uint32_t u32;
typedef uint64_t u64;

// ---------------- scratch ----------------
__device__ __align__(16) float g_KVp[BATCH][SPLIT][DIM * DIM];
__device__ __align__(16) float g_Ksump[BATCH][SPLIT][DIM];
__device__ __align__(16) __nv_bfloat16 g_KVThi[BATCH][DIM * DIM]; // KV^T (row e, col d)
__device__ __align__(16) __nv_bfloat16 g_KVTlo[BATCH][DIM * DIM];
__device__ __align__(16) float g_Ksum[BATCH][DIM];

// ---------------- helpers ----------------
__device__ __forceinline__ u32 smem_u32(const void* p) {
    u32 a;
    asm("{ .reg .u64 t; cvta.to.shared.u64 t, %1; cvt.u32.u64 %0, t; }" : "=r"(a) : "l"(p));
    return a;
}
__device__ __forceinline__ void ldsm4(u32& r0, u32& r1, u32& r2, u32& r3, u32 addr) {
    asm volatile("ldmatrix.sync.aligned.m8n8.x4.shared.b16 {%0,%1,%2,%3}, [%4];"
                 : "=r"(r0), "=r"(r1), "=r"(r2), "=r"(r3) : "r"(addr));
}
__device__ __forceinline__ void mma16816(float* c, u32 a0, u32 a1, u32 a2, u32 a3,
                                         u32 b0, u32 b1) {
    asm volatile("mma.sync.aligned.m16n8k16.row.col.f32.bf16.bf16.f32 "
                 "{%0,%1,%2,%3}, {%4,%5,%6,%7}, {%8,%9}, {%0,%1,%2,%3};"
                 : "+f"(c[0]), "+f"(c[1]), "+f"(c[2]), "+f"(c[3])
                 : "r"(a0), "r"(a1), "r"(a2), "r"(a3), "r"(b0), "r"(b1));
}
#define MBAR_INIT(mbar, cnt) \
    asm volatile("mbarrier.init.shared.b64 [%0], %1;" :: "r"((u32)(mbar)), "r"((u32)(cnt)) : "memory")
#define MBAR_ARRIVE(mbar) \
    asm volatile("mbarrier.arrive.release.cta.shared::cta.b64 _, [%0];" :: "r"((u32)(mbar)) : "memory")
#define MBAR_WAIT(mbar, parity) do { \
    u32 _m = (u32)(mbar), _p = (u32)(parity), _done; \
    asm volatile("{ .reg .pred p; mbarrier.try_wait.parity.acquire.cta.shared::cta.b64 p, [%1], %2; selp.b32 %0, 1, 0, p; }" \
                 : "=r"(_done) : "r"(_m), "r"(_p) : "memory"); \
    if (!_done) { \
        asm volatile("{ .reg .pred P1; WL_%=: mbarrier.try_wait.parity.acquire.cta.shared::cta.b64 P1, [%0], %1, 0x989680; @P1 bra.uni WD_%=; bra.uni WL_%=; WD_%=: }" \
                     :: "r"(_m), "r"(_p) : "memory"); \
    } } while (0)

__device__ __forceinline__ float phi(float x) { return x > 0.0f ? x + 1.0f : __expf(x); }
__device__ __forceinline__ u32 pack_bf16(float a, float b) {
    __nv_bfloat162 h = __floats2bfloat162_rn(a, b);
    return *reinterpret_cast<u32*>(&h);
}
__device__ __forceinline__ void split2(float a, float b, u32& hi, u32& lo) {
    float ha = __bfloat162float(__float2bfloat16(a));
    float hb = __bfloat162float(__float2bfloat16(b));
    hi = pack_bf16(ha, hb);
    lo = pack_bf16(a - ha, b - hb);
}

// ====================================================================
// k1: KV[d][e] = sum_n phi(K[d,n]) * V[e,n].  Warp-specialized.
// 384 thr: warps 0-7 consumers (MMA), 8-11 producers (load+convert).
// 2 smem stages, each: KHI KLO VHI VLO [128 rows][64 tok] pitch 144B.
// ====================================================================
#define P1B 144
#define ST1 73728                      // bytes per stage (4 * 128 * 144)
#define K1_KSB 147456                  // ksum buffer 128*16*4 = 8192
#define K1_BAR 155648                  // full0 full1 empty0 empty1
#define K1_SMEM 155712

__global__ __launch_bounds__(384, 1)
void k1_mma(const float* __restrict__ k, const float* __restrict__ v) {
    extern __shared__ __align__(16) char sm[];
    const u32 sb = smem_u32(sm);
    const int b = blockIdx.y, s = blockIdx.x;
    const int tid = threadIdx.x, wid = tid >> 5, lane = tid & 31;
    const u32 FULL0 = sb + K1_BAR, FULL1 = FULL0 + 8, EMPTY0 = FULL0 + 16, EMPTY1 = FULL0 + 24;

    if (tid == 0) {
        MBAR_INIT(FULL0, 128);  MBAR_INIT(FULL1, 128);
        MBAR_INIT(EMPTY0, 256); MBAR_INIT(EMPTY1, 256);
    }
    __syncthreads();

    const float* kb = k + (size_t)b * DIM * NTOK + (size_t)s * CHUNK;
    const float* vb = v + (size_t)b * DIM * NTOK + (size_t)s * CHUNK;

    if (wid < 8) {
        // ================= consumer =================
        const int wd = wid >> 2, we = wid & 3;     // 64d x 32e warp tile
        const int rA = (lane & 7) + ((lane & 8) ? 8 : 0);
        const int cA = (lane & 16) ? 16 : 0;
        const int rB = (lane & 7) + ((lane & 16) ? 8 : 0);
        const int cB = (lane & 8) ? 16 : 0;

        float acc[4][4][4];
#pragma unroll
        for (int i = 0; i < 4; i++)
#pragma unroll
            for (int j = 0; j < 4; j++)
#pragma unroll
                for (int r = 0; r < 4; r++) acc[i][j][r] = 0.f;

        int pf0 = 0, pf1 = 0;
        for (int iter = 0; iter < ITERS; iter++) {
            const int st = iter & 1;
            if (st == 0) { MBAR_WAIT(FULL0, pf0); pf0 ^= 1; }
            else         { MBAR_WAIT(FULL1, pf1); pf1 ^= 1; }
            const u32 base = sb + st * ST1;
#pragma unroll
            for (int kk = 0; kk < 4; kk++) {
                u32 bh[8], bl[8];
#pragma unroll
                for (int g = 0; g < 2; g++) {
                    const u32 boff = (u32)((we * 32 + g * 16 + rB) * P1B + kk * 32 + cB);
                    ldsm4(bh[g*4+0], bh[g*4+1], bh[g*4+2], bh[g*4+3], base + 36864 + boff);
                    ldsm4(bl[g*4+0], bl[g*4+1], bl[g*4+2], bl[g*4+3], base + 55296 + boff);
                }
#pragma unroll
                for (int mt = 0; mt < 4; mt++) {
                    const u32 aoff = (u32)((wd * 64 + mt * 16 + rA) * P1B + kk * 32 + cA);
                    u32 ah0, ah1, ah2, ah3, al0, al1, al2, al3;
                    ldsm4(ah0, ah1, ah2, ah3, base + 0     + aoff);
                    ldsm4(al0, al1, al2, al3, base + 18432 + aoff);
#pragma unroll
                    for (int nt = 0; nt < 4; nt++) {
                        float* c = acc[mt][nt];
                        const int bi = (nt >> 1) * 4 + (nt & 1) * 2;
                        mma16816(c, ah0, ah1, ah2, ah3, bh[bi], bh[bi+1]);
                        mma16816(c, ah0, ah1, ah2, ah3, bl[bi], bl[bi+1]);
                        mma16816(c, al0, al1, al2, al3, bh[bi], bh[bi+1]);
                    }
                }
            }
            MBAR_ARRIVE(st == 0 ? EMPTY0 : EMPTY1);
        }
        // write fp32 partial
        float* dst = &g_KVp[b][s][0];
        const int g = lane >> 2, tig = lane & 3;
#pragma unroll
        for (int mt = 0; mt < 4; mt++)
#pragma unroll
            for (int nt = 0; nt < 4; nt++) {
                const int d0 = wd * 64 + mt * 16 + g;
                const int e0 = we * 32 + nt * 8 + tig * 2;
                float* c = acc[mt][nt];
                *(float2*)(dst + d0 * DIM + e0)       = make_float2(c[0], c[1]);
                *(float2*)(dst + (d0 + 8) * DIM + e0) = make_float2(c[2], c[3]);
            }
    } else {
        // ================= producer =================
        const int ptid = tid - 256;        // 0..127
        const int n4 = ptid & 15, dr = ptid >> 4;   // 8 rows per pass
        float ksum_l[16];
#pragma unroll
        for (int p = 0; p < 16; p++) ksum_l[p] = 0.f;

        int pe0 = 0, pe1 = 0;
        for (int iter = 0; iter < ITERS; iter++) {
            const int st = iter & 1;
            if (iter >= 2) {
                if (st == 0) { MBAR_WAIT(EMPTY0, pe0); pe0 ^= 1; }
                else         { MBAR_WAIT(EMPTY1, pe1); pe1 ^= 1; }
            }
            const int n0 = iter * 64;
            char* stp = sm + st * ST1;
#pragma unroll
            for (int p = 0; p < 16; p++) {
                const int d = p * 8 + dr;
                const u32 off = (u32)(d * P1B + n4 * 8);
                float4 kx = *(const float4*)(kb + (size_t)d * NTOK + n0 + n4 * 4);
                float f0 = phi(kx.x), f1 = phi(kx.y), f2 = phi(kx.z), f3 = phi(kx.w);
                ksum_l[p] += (f0 + f1) + (f2 + f3);
                uint2 hi, lo;
                split2(f0, f1, hi.x, lo.x);
                split2(f2, f3, hi.y, lo.y);
                *(uint2*)(stp + 0     + off) = hi;
                *(uint2*)(stp + 18432 + off) = lo;
                float4 vx = *(const float4*)(vb + (size_t)d * NTOK + n0 + n4 * 4);
                split2(vx.x, vx.y, hi.x, lo.x);
                split2(vx.z, vx.w, hi.y, lo.y);
                *(uint2*)(stp + 36864 + off) = hi;
                *(uint2*)(stp + 55296 + off) = lo;
            }
            MBAR_ARRIVE(st == 0 ? FULL0 : FULL1);
        }
        // ksum reduce (dedicated buffer; consumers never touch it)
        float* kbuf = (float*)(sm + K1_KSB);
#pragma unroll
        for (int p = 0; p < 16; p++) kbuf[(p * 8 + dr) * 16 + n4] = ksum_l[p];
        asm volatile("bar.sync 1, 128;" ::: "memory");
        {
            float sum = 0.f;
#pragma unroll
            for (int i = 0; i < 16; i++) sum += kbuf[ptid * 16 + i];
            g_Ksump[b][s][ptid] = sum;
        }
    }
}

// ====================================================================
// k2: reduce partials -> KV^T bf16 hi/lo + Ksum fp32
// ====================================================================
__global__ __launch_bounds__(256)
void k2_reduce() {
    const int idx = blockIdx.x * 256 + threadIdx.x;
    if (idx < BATCH * DIM * DIM) {
        const int b = idx >> 14, e = idx & 127, d = (idx >> 7) & 127;
        float sum = 0.f;
#pragma unroll
        for (int p = 0; p < SPLIT; p++) sum += g_KVp[b][p][d * DIM + e];
        __nv_bfloat16 h = __float2bfloat16(sum);
        g_KVThi[b][e * DIM + d] = h;
        g_KVTlo[b][e * DIM + d] = __float2bfloat16(sum - __bfloat162float(h));
    }
    if (idx < BATCH * DIM) {
        const int b = idx >> 7, d = idx & 127;
        float sum = 0.f;
#pragma unroll
        for (int p = 0; p < SPLIT; p++) sum += g_Ksump[b][p][d];
        g_Ksum[b][d] = sum;
    }
}

// ====================================================================
// k3: out^T[e][t] = z(t) * sum_d KV^T[e,d] * phi(Q[t,d]).  Warp-specialized.
// KV^T resident in smem; Q staged (2 stages of 64 tokens).
// ====================================================================
#define P3B 272
#define K3_AHI 0
#define K3_ALO 34816
#define K3_QST 69632                   // stage s at K3_QST + s*34816 (QHI, QLO+17408)
#define K3_KS  139264                  // 128 f32
#define K3_ZS  139776                  // 2 x 64 f32
#define K3_DEN 140288                  // 2 x 2 x 64 f32
#define K3_BAR 141312
#define K3_SMEM 141376

__global__ __launch_bounds__(384, 1)
void k3_mma(const float* __restrict__ q, float* __restrict__ out) {
    extern __shared__ __align__(16) char sm[];
    const u32 sb = smem_u32(sm);
    const int b = blockIdx.y, s = blockIdx.x;
    const int tid = threadIdx.x, wid = tid >> 5, lane = tid & 31;
    const u32 FULL0 = sb + K3_BAR, FULL1 = FULL0 + 8, EMPTY0 = FULL0 + 16, EMPTY1 = FULL0 + 24;

    if (tid == 0) {
        MBAR_INIT(FULL0, 128);  MBAR_INIT(FULL1, 128);
        MBAR_INIT(EMPTY0, 256); MBAR_INIT(EMPTY1, 256);
    }
    // resident KV^T hi/lo + ksum
    for (int i = tid; i < DIM * 64; i += 384) {
        const int e = i >> 6, dp = i & 63;
        const u32 off = (u32)(e * P3B + dp * 4);
        *(u32*)(sm + K3_AHI + off) = *(const u32*)(&g_KVThi[b][e * DIM + dp * 2]);
        *(u32*)(sm + K3_ALO + off) = *(const u32*)(&g_KVTlo[b][e * DIM + dp * 2]);
    }
    float* ks = (float*)(sm + K3_KS);
    float* zs = (float*)(sm + K3_ZS);
    float* denp = (float*)(sm + K3_DEN);
    if (tid < 128) ks[tid] = g_Ksum[b][tid];
    __syncthreads();

    const float* qb = q + (size_t)b * DIM * NTOK;
    float* ob = out + (size_t)b * DIM * NTOK;

    if (wid < 8) {
        // ================= consumer =================
        const int we = wid >> 2, wt = wid & 3;     // 64e x 16t warp tile
        const int rA = (lane & 7) + ((lane & 8) ? 8 : 0);
        const int cA = (lane & 16) ? 16 : 0;
        const int rB = (lane & 7) + ((lane & 16) ? 8 : 0);
        const int cB = (lane & 8) ? 16 : 0;
        const int g = lane >> 2, tig = lane & 3;

        int pf0 = 0, pf1 = 0;
        for (int tile = 0; tile < ITERS; tile++) {
            const int st = tile & 1;
            if (st == 0) { MBAR_WAIT(FULL0, pf0); pf0 ^= 1; }
            else         { MBAR_WAIT(FULL1, pf1); pf1 ^= 1; }
            const u32 qbase = sb + K3_QST + st * 34816;
            const int T0 = s * CHUNK + tile * 64;

            float acc[4][2][4];
#pragma unroll
            for (int i = 0; i < 4; i++)
#pragma unroll
                for (int j = 0; j < 2; j++)
#pragma unroll
                    for (int r = 0; r < 4; r++) acc[i][j][r] = 0.f;
#pragma unroll
            for (int kk = 0; kk < 8; kk++) {
                const u32 boff = (u32)((wt * 16 + rB) * P3B + kk * 32 + cB);
                u32 bh0, bh1, bh2, bh3, bl0, bl1, bl2, bl3;
                ldsm4(bh0, bh1, bh2, bh3, qbase + boff);
                ldsm4(bl0, bl1, bl2, bl3, qbase + 17408 + boff);
#pragma unroll
                for (int mt = 0; mt < 4; mt++) {
                    const u32 aoff = (u32)((we * 64 + mt * 16 + rA) * P3B + kk * 32 + cA);
                    u32 ah0, ah1, ah2, ah3, al0, al1, al2, al3;
                    ldsm4(ah0, ah1, ah2, ah3, sb + K3_AHI + aoff);
                    ldsm4(al0, al1, al2, al3, sb + K3_ALO + aoff);
                    mma16816(acc[mt][0], ah0, ah1, ah2, ah3, bh0, bh1);
                    mma16816(acc[mt][0], ah0, ah1, ah2, ah3, bl0, bl1);
                    mma16816(acc[mt][0], al0, al1, al2, al3, bh0, bh1);
                    mma16816(acc[mt][1], ah0, ah1, ah2, ah3, bh2, bh3);
                    mma16816(acc[mt][1], ah0, ah1, ah2, ah3, bl2, bl3);
                    mma16816(acc[mt][1], al0, al1, al2, al3, bh2, bh3);
                }
            }
            // epilogue: z-scale + store out^T
#pragma unroll
            for (int mt = 0; mt < 4; mt++)
#pragma unroll
                for (int nt = 0; nt < 2; nt++) {
                    const int e0 = we * 64 + mt * 16 + g;
                    const int lt = wt * 16 + nt * 8 + tig * 2;
                    const float z0 = zs[st * 64 + lt], z1 = zs[st * 64 + lt + 1];
                    float* c = acc[mt][nt];
                    *(float2*)(ob + (size_t)e0 * NTOK + T0 + lt) =
                        make_float2(c[0] * z0, c[1] * z1);
                    *(float2*)(ob + (size_t)(e0 + 8) * NTOK + T0 + lt) =
                        make_float2(c[2] * z0, c[3] * z1);
                }
            MBAR_ARRIVE(st == 0 ? EMPTY0 : EMPTY1);
        }
    } else {
        // ================= producer =================
        const int ptid = tid - 256;            // 0..127
        const int tl = ptid & 63, half = ptid >> 6;
        int pe0 = 0, pe1 = 0;
        for (int tile = 0; tile < ITERS; tile++) {
            const int st = tile & 1;
            if (tile >= 2) {
                if (st == 0) { MBAR_WAIT(EMPTY0, pe0); pe0 ^= 1; }
                else         { MBAR_WAIT(EMPTY1, pe1); pe1 ^= 1; }
            }
            const int T0 = s * CHUNK + tile * 64;
            char* qsm = sm + K3_QST + st * 34816;
            const float* qp = qb + T0 + tl;
            float den_l = 0.f;
#pragma unroll
            for (int j = 0; j < 32; j++) {
                const int dp = half * 32 + j, d0 = dp * 2;
                float f0 = phi(qp[(size_t)d0 * NTOK]);
                float f1 = phi(qp[(size_t)(d0 + 1) * NTOK]);
                u32 hi, lo;
                split2(f0, f1, hi, lo);
                const u32 off = (u32)(tl * P3B + dp * 4);
                *(u32*)(qsm + off)         = hi;
                *(u32*)(qsm + 17408 + off) = lo;
                den_l += f0 * ks[d0] + f1 * ks[d0 + 1];
            }
            denp[(st * 2 + half) * 64 + tl] = den_l;
            asm volatile("bar.sync 1, 128;" ::: "memory");
            if (ptid < 64)
                zs[st * 64 + ptid] = 1.0f / (denp[st * 128 + ptid] + denp[st * 128 + 64 + ptid] + EPS);
            MBAR_ARRIVE(st == 0 ? FULL0 : FULL1);
        }
    }
}

// ====================================================================
extern "C" void kernel_launch(void* const* d_in, const int* in_sizes, int n_in,
                              void* d_out, int out_size) {
    const float* q = (const float*)d_in[0];
    const float* k = (const float*)d_in[1];
    const float* v = (const float*)d_in[2];
    float* out = (float*)d_out;

    cudaFuncSetAttribute(k1_mma, cudaFuncAttributeMaxDynamicSharedMemorySize, K1_SMEM);
    cudaFuncSetAttribute(k3_mma, cudaFuncAttributeMaxDynamicSharedMemorySize, K3_SMEM);

    k1_mma<<<dim3(SPLIT, BATCH), 384, K1_SMEM>>>(k, v);
    k2_reduce<<<(BATCH * DIM * DIM + 255) / 256, 256>>>();
    k3_mma<<<dim3(SPLIT, BATCH), 384, K3_SMEM>>>(q, out);
}

// round 6
// speedup vs baseline: 2.6004x; 2.6004x over previous
#include <cuda_runtime.h>
#include <cuda_bf16.h>
#include <cstdint>

#define BATCH 8
#define DIM   128
#define NTOK  32768
#define SPLIT 16
#define CHUNK (NTOK/SPLIT)     // 2048 tokens per CTA
#define ITERS (CHUNK/64)       // 32 stages of 64 tokens
#define EPS 1e-8f

typedef uint32_t u32;
typedef uint64_t u64;

// ---------------- scratch ----------------
__device__ __align__(16) float g_KVp[BATCH][SPLIT][DIM * DIM];
__device__ __align__(16) float g_Ksump[BATCH][SPLIT][DIM];
__device__ __align__(16) __nv_bfloat16 g_KVThi[BATCH][DIM * DIM]; // KV^T (row e, col d)
__device__ __align__(16) __nv_bfloat16 g_KVTlo[BATCH][DIM * DIM];
__device__ __align__(16) float g_Ksum[BATCH][DIM];

// ---------------- helpers ----------------
__device__ __forceinline__ u32 smem_u32(const void* p) {
    u32 a;
    asm("{ .reg .u64 t; cvta.to.shared.u64 t, %1; cvt.u32.u64 %0, t; }" : "=r"(a) : "l"(p));
    return a;
}
__device__ __forceinline__ void ldsm4(u32& r0, u32& r1, u32& r2, u32& r3, u32 addr) {
    asm volatile("ldmatrix.sync.aligned.m8n8.x4.shared.b16 {%0,%1,%2,%3}, [%4];"
                 : "=r"(r0), "=r"(r1), "=r"(r2), "=r"(r3) : "r"(addr));
}
__device__ __forceinline__ void mma16816(float* c, u32 a0, u32 a1, u32 a2, u32 a3,
                                         u32 b0, u32 b1) {
    asm volatile("mma.sync.aligned.m16n8k16.row.col.f32.bf16.bf16.f32 "
                 "{%0,%1,%2,%3}, {%4,%5,%6,%7}, {%8,%9}, {%0,%1,%2,%3};"
                 : "+f"(c[0]), "+f"(c[1]), "+f"(c[2]), "+f"(c[3])
                 : "r"(a0), "r"(a1), "r"(a2), "r"(a3), "r"(b0), "r"(b1));
}
__device__ __forceinline__ void cpa16(u32 dst, const void* src) {
    asm volatile("cp.async.cg.shared.global [%0], [%1], 16;" :: "r"(dst), "l"(src));
}
#define CP_COMMIT() asm volatile("cp.async.commit_group;" ::: "memory")
#define CP_WAIT0()  asm volatile("cp.async.wait_group 0;" ::: "memory")

__device__ __forceinline__ float phi(float x) { return x > 0.0f ? x + 1.0f : __expf(x); }
__device__ __forceinline__ u32 pack_bf16(float a, float b) {
    __nv_bfloat162 h = __floats2bfloat162_rn(a, b);
    return *reinterpret_cast<u32*>(&h);
}
__device__ __forceinline__ void split2(float a, float b, u32& hi, u32& lo) {
    float ha = __bfloat162float(__float2bfloat16(a));
    float hb = __bfloat162float(__float2bfloat16(b));
    hi = pack_bf16(ha, hb);
    lo = pack_bf16(a - ha, b - hb);
}

// ====================================================================
// k1: KV[d][e] = sum_n phi(K[d,n]) * V[e,n]
// 256 threads. Stages of 64 tokens. cp.async raw prefetch under MMA.
// bf16 stage s: KHI/KLO/VHI/VLO [128 rows][64 tok], pitch 144B.
// raw staging: K,V [128 rows][64 tok] fp32, pitch 256B.
// ====================================================================
#define P1B 144
#define ST1 73728
#define K1_RAWK 147456
#define K1_RAWV 180224
#define K1_KSB  212992
#define K1_SMEM 221184

__global__ __launch_bounds__(256, 1)
void k1_mma(const float* __restrict__ k, const float* __restrict__ v) {
    extern __shared__ __align__(16) char sm[];
    const u32 sb = smem_u32(sm);
    const int b = blockIdx.y, s = blockIdx.x;
    const int tid = threadIdx.x, wid = tid >> 5, lane = tid & 31;
    const int n4 = tid & 15, dr = tid >> 4;
    const int wd = wid >> 2, we = wid & 3;     // 64d x 32e warp tile

    const float* kb = k + (size_t)b * DIM * NTOK + (size_t)s * CHUNK;
    const float* vb = v + (size_t)b * DIM * NTOK + (size_t)s * CHUNK;

    const int rA = (lane & 7) + ((lane & 8) ? 8 : 0);
    const int cA = (lane & 16) ? 16 : 0;
    const int rB = (lane & 7) + ((lane & 16) ? 8 : 0);
    const int cB = (lane & 8) ? 16 : 0;

    float acc[4][4][4];
#pragma unroll
    for (int i = 0; i < 4; i++)
#pragma unroll
        for (int j = 0; j < 4; j++)
#pragma unroll
            for (int r = 0; r < 4; r++) acc[i][j][r] = 0.f;
    float ksum_l[8] = {0.f, 0.f, 0.f, 0.f, 0.f, 0.f, 0.f, 0.f};

    // issue = prefetch raw fp32 tile for token offset n0 (8 K + 8 V chunks/thread)
    auto issue = [&](int n0) {
#pragma unroll
        for (int c = 0; c < 8; c++) {
            const int ci = tid + c * 256;          // 0..2047
            const int d = ci >> 4, col = ci & 15;
            cpa16(sb + K1_RAWK + d * 256 + col * 16, kb + (size_t)d * NTOK + n0 + col * 4);
            cpa16(sb + K1_RAWV + d * 256 + col * 16, vb + (size_t)d * NTOK + n0 + col * 4);
        }
        CP_COMMIT();
    };

    issue(0);

    for (int iter = 0; iter < ITERS; iter++) {
        CP_WAIT0();
        __syncthreads();
        // ---- convert raw smem -> bf16 stage (iter&1) ----
        {
            char* stp = sm + (iter & 1) * ST1;
#pragma unroll
            for (int p = 0; p < 8; p++) {
                const int d = p * 16 + dr;
                const u32 roff = (u32)(d * 256 + n4 * 16);
                const u32 off = (u32)(d * P1B + n4 * 8);
                float4 kx = *(const float4*)(sm + K1_RAWK + roff);
                float f0 = phi(kx.x), f1 = phi(kx.y), f2 = phi(kx.z), f3 = phi(kx.w);
                ksum_l[p] += (f0 + f1) + (f2 + f3);
                uint2 hi, lo;
                split2(f0, f1, hi.x, lo.x);
                split2(f2, f3, hi.y, lo.y);
                *(uint2*)(stp + 0     + off) = hi;
                *(uint2*)(stp + 18432 + off) = lo;
                float4 vx = *(const float4*)(sm + K1_RAWV + roff);
                split2(vx.x, vx.y, hi.x, lo.x);
                split2(vx.z, vx.w, hi.y, lo.y);
                *(uint2*)(stp + 36864 + off) = hi;
                *(uint2*)(stp + 55296 + off) = lo;
            }
        }
        __syncthreads();
        if (iter + 1 < ITERS) issue((iter + 1) * 64);   // DMA overlaps MMA below
        // ---- MMA on stage (iter&1) ----
        const u32 base = sb + (iter & 1) * ST1;
#pragma unroll
        for (int kk = 0; kk < 4; kk++) {
            u32 bh[8], bl[8];
#pragma unroll
            for (int g = 0; g < 2; g++) {
                const u32 boff = (u32)((we * 32 + g * 16 + rB) * P1B + kk * 32 + cB);
                ldsm4(bh[g*4+0], bh[g*4+1], bh[g*4+2], bh[g*4+3], base + 36864 + boff);
                ldsm4(bl[g*4+0], bl[g*4+1], bl[g*4+2], bl[g*4+3], base + 55296 + boff);
            }
#pragma unroll
            for (int mt = 0; mt < 4; mt++) {
                const u32 aoff = (u32)((wd * 64 + mt * 16 + rA) * P1B + kk * 32 + cA);
                u32 ah0, ah1, ah2, ah3, al0, al1, al2, al3;
                ldsm4(ah0, ah1, ah2, ah3, base + 0     + aoff);
                ldsm4(al0, al1, al2, al3, base + 18432 + aoff);
#pragma unroll
                for (int nt = 0; nt < 4; nt++) {
                    float* c = acc[mt][nt];
                    const int bi = (nt >> 1) * 4 + (nt & 1) * 2;
                    mma16816(c, ah0, ah1, ah2, ah3, bh[bi], bh[bi+1]);
                    mma16816(c, ah0, ah1, ah2, ah3, bl[bi], bl[bi+1]);
                    mma16816(c, al0, al1, al2, al3, bh[bi], bh[bi+1]);
                }
            }
        }
    }
    __syncthreads();
    // ---- ksum reduce ----
    float* kbuf = (float*)(sm + K1_KSB);
#pragma unroll
    for (int p = 0; p < 8; p++) kbuf[(p * 16 + dr) * 16 + n4] = ksum_l[p];
    __syncthreads();
    if (tid < 128) {
        float sum = 0.f;
#pragma unroll
        for (int i = 0; i < 16; i++) sum += kbuf[tid * 16 + i];
        g_Ksump[b][s][tid] = sum;
    }
    // ---- write fp32 KV partial ----
    float* dst = &g_KVp[b][s][0];
    const int g = lane >> 2, tig = lane & 3;
#pragma unroll
    for (int mt = 0; mt < 4; mt++)
#pragma unroll
        for (int nt = 0; nt < 4; nt++) {
            const int d0 = wd * 64 + mt * 16 + g;
            const int e0 = we * 32 + nt * 8 + tig * 2;
            float* c = acc[mt][nt];
            *(float2*)(dst + d0 * DIM + e0)       = make_float2(c[0], c[1]);
            *(float2*)(dst + (d0 + 8) * DIM + e0) = make_float2(c[2], c[3]);
        }
}

// ====================================================================
// k2: reduce partials -> KV^T bf16 hi/lo + Ksum fp32
// ====================================================================
__global__ __launch_bounds__(256)
void k2_reduce() {
    const int idx = blockIdx.x * 256 + threadIdx.x;
    if (idx < BATCH * DIM * DIM) {
        const int b = idx >> 14, e = idx & 127, d = (idx >> 7) & 127;
        float sum = 0.f;
#pragma unroll
        for (int p = 0; p < SPLIT; p++) sum += g_KVp[b][p][d * DIM + e];
        __nv_bfloat16 h = __float2bfloat16(sum);
        g_KVThi[b][e * DIM + d] = h;
        g_KVTlo[b][e * DIM + d] = __float2bfloat16(sum - __bfloat162float(h));
    }
    if (idx < BATCH * DIM) {
        const int b = idx >> 7, d = idx & 127;
        float sum = 0.f;
#pragma unroll
        for (int p = 0; p < SPLIT; p++) sum += g_Ksump[b][p][d];
        g_Ksum[b][d] = sum;
    }
}

// ====================================================================
// k3: out^T[e][t] = z(t) * sum_d KV^T[e,d] * phi(Q[t,d])
// KV^T resident; Q raw cp.async staged; bf16 Q double-buffered.
// ====================================================================
#define P3B 272
#define K3_AHI 0
#define K3_ALO 34816
#define K3_QST 69632          // stage s: QHI at +s*34816, QLO at +17408
#define K3_RAW 139264         // [128 d][64 t] fp32, pitch 256B
#define K3_KS  172032
#define K3_ZS  172544
#define K3_DEN 172800
#define K3_SMEM 173824

__global__ __launch_bounds__(256, 1)
void k3_mma(const float* __restrict__ q, float* __restrict__ out) {
    extern __shared__ __align__(16) char sm[];
    const u32 sb = smem_u32(sm);
    const int b = blockIdx.y, s = blockIdx.x;
    const int tid = threadIdx.x, wid = tid >> 5, lane = tid & 31;
    const int we = wid >> 2, wt = wid & 3;     // 64e x 16t warp tile

    // resident KV^T hi/lo + ksum
    for (int i = tid; i < DIM * 64; i += 256) {
        const int e = i >> 6, dp = i & 63;
        const u32 off = (u32)(e * P3B + dp * 4);
        *(u32*)(sm + K3_AHI + off) = *(const u32*)(&g_KVThi[b][e * DIM + dp * 2]);
        *(u32*)(sm + K3_ALO + off) = *(const u32*)(&g_KVTlo[b][e * DIM + dp * 2]);
    }
    float* ks = (float*)(sm + K3_KS);
    float* zs = (float*)(sm + K3_ZS);
    float* denp = (float*)(sm + K3_DEN);
    if (tid < 128) ks[tid] = g_Ksum[b][tid];

    const float* qb = q + (size_t)b * DIM * NTOK;
    float* ob = out + (size_t)b * DIM * NTOK;

    auto issue = [&](int T0) {
#pragma unroll
        for (int c = 0; c < 8; c++) {
            const int ci = tid + c * 256;
            const int d = ci >> 4, col = ci & 15;
            cpa16(sb + K3_RAW + d * 256 + col * 16, qb + (size_t)d * NTOK + T0 + col * 4);
        }
        CP_COMMIT();
    };

    issue(s * CHUNK);

    const int rA = (lane & 7) + ((lane & 8) ? 8 : 0);
    const int cA = (lane & 16) ? 16 : 0;
    const int rB = (lane & 7) + ((lane & 16) ? 8 : 0);
    const int cB = (lane & 8) ? 16 : 0;
    const int g = lane >> 2, tig = lane & 3;

    const int tl = tid & 63, qq = tid >> 6;    // convert roles: token tl, quarter qq

    for (int tile = 0; tile < ITERS; tile++) {
        const int st = tile & 1;
        const int T0 = s * CHUNK + tile * 64;
        CP_WAIT0();
        __syncthreads();
        // ---- convert raw -> Q bf16 stage st (+ den partials), STS.128 ----
        {
            char* qsm = sm + K3_QST + st * 34816;
            float den_l = 0.f;
#pragma unroll
            for (int gg = 0; gg < 4; gg++) {
                uint4 hi4, lo4;
                u32* hp = (u32*)&hi4; u32* lp = (u32*)&lo4;
#pragma unroll
                for (int j = 0; j < 4; j++) {
                    const int dp = qq * 16 + gg * 4 + j, d0 = dp * 2;
                    float f0 = phi(*(const float*)(sm + K3_RAW + d0 * 256 + tl * 4));
                    float f1 = phi(*(const float*)(sm + K3_RAW + (d0 + 1) * 256 + tl * 4));
                    split2(f0, f1, hp[j], lp[j]);
                    den_l += f0 * ks[d0] + f1 * ks[d0 + 1];
                }
                const u32 off = (u32)(tl * P3B + (qq * 16 + gg * 4) * 4);
                *(uint4*)(qsm + off)         = hi4;
                *(uint4*)(qsm + 17408 + off) = lo4;
            }
            denp[qq * 64 + tl] = den_l;
        }
        __syncthreads();
        if (tid < 64)
            zs[tid] = 1.0f / (denp[tid] + denp[64 + tid] + denp[128 + tid] + denp[192 + tid] + EPS);
        if (tile + 1 < ITERS) issue(T0 + 64);
        __syncthreads();

        // ---- MMA ----
        const u32 qbase = sb + K3_QST + st * 34816;
        float acc[4][2][4];
#pragma unroll
        for (int i = 0; i < 4; i++)
#pragma unroll
            for (int j = 0; j < 2; j++)
#pragma unroll
                for (int r = 0; r < 4; r++) acc[i][j][r] = 0.f;
#pragma unroll
        for (int kk = 0; kk < 8; kk++) {
            const u32 boff = (u32)((wt * 16 + rB) * P3B + kk * 32 + cB);
            u32 bh0, bh1, bh2, bh3, bl0, bl1, bl2, bl3;
            ldsm4(bh0, bh1, bh2, bh3, qbase + boff);
            ldsm4(bl0, bl1, bl2, bl3, qbase + 17408 + boff);
#pragma unroll
            for (int mt = 0; mt < 4; mt++) {
                const u32 aoff = (u32)((we * 64 + mt * 16 + rA) * P3B + kk * 32 + cA);
                u32 ah0, ah1, ah2, ah3, al0, al1, al2, al3;
                ldsm4(ah0, ah1, ah2, ah3, sb + K3_AHI + aoff);
                ldsm4(al0, al1, al2, al3, sb + K3_ALO + aoff);
                mma16816(acc[mt][0], ah0, ah1, ah2, ah3, bh0, bh1);
                mma16816(acc[mt][0], ah0, ah1, ah2, ah3, bl0, bl1);
                mma16816(acc[mt][0], al0, al1, al2, al3, bh0, bh1);
                mma16816(acc[mt][1], ah0, ah1, ah2, ah3, bh2, bh3);
                mma16816(acc[mt][1], ah0, ah1, ah2, ah3, bl2, bl3);
                mma16816(acc[mt][1], al0, al1, al2, al3, bh2, bh3);
            }
        }
        // ---- epilogue: z-scale + store out^T ----
#pragma unroll
        for (int mt = 0; mt < 4; mt++)
#pragma unroll
            for (int nt = 0; nt < 2; nt++) {
                const int e0 = we * 64 + mt * 16 + g;
                const int lt = wt * 16 + nt * 8 + tig * 2;
                const float z0 = zs[lt], z1 = zs[lt + 1];
                float* c = acc[mt][nt];
                *(float2*)(ob + (size_t)e0 * NTOK + T0 + lt) =
                    make_float2(c[0] * z0, c[1] * z1);
                *(float2*)(ob + (size_t)(e0 + 8) * NTOK + T0 + lt) =
                    make_float2(c[2] * z0, c[3] * z1);
            }
        __syncthreads();   // zs/den reuse safe
    }
}

// ====================================================================
extern "C" void kernel_launch(void* const* d_in, const int* in_sizes, int n_in,
                              void* d_out, int out_size) {
    const float* q = (const float*)d_in[0];
    const float* k = (const float*)d_in[1];
    const float* v = (const float*)d_in[2];
    float* out = (float*)d_out;

    cudaFuncSetAttribute(k1_mma, cudaFuncAttributeMaxDynamicSharedMemorySize, K1_SMEM);
    cudaFuncSetAttribute(k3_mma, cudaFuncAttributeMaxDynamicSharedMemorySize, K3_SMEM);

    k1_mma<<<dim3(SPLIT, BATCH), 256, K1_SMEM>>>(k, v);
    k2_reduce<<<(BATCH * DIM * DIM + 255) / 256, 256>>>();
    k3_mma<<<dim3(SPLIT, BATCH), 256, K3_SMEM>>>(q, out);
}